// round 1
// baseline (speedup 1.0000x reference)
#include <cuda_runtime.h>
#include <cuda_bf16.h>

// Problem constants
#define BB 8
#define NN 1024
#define TT 64
#define HH 64
#define BT 512          // B*T
#define ELEMS (BB*NN*TT)  // 524288

// Scratch (no allocations allowed)
__device__ float g_X[1024 * 1024];   // X[i*1024 + c], c in [0,512)=x1, [512,1024)=mask
__device__ float g_U[1024 * 1024];   // U[j*1024 + c]
__device__ float g_S[1024];          // column sums of adj
__device__ float g_coef[512];        // r1..r6, wro, wro*a  (8 x 64)

// ---------------------------------------------------------------------------
// Kernel 1: fold all linear layers into 6 coefficient vectors (h == 0 collapse)
// ---------------------------------------------------------------------------
__global__ void coef_kernel(const float* __restrict__ Win, const float* __restrict__ bin,
                            const float* __restrict__ Wgc, const float* __restrict__ bgc,
                            const float* __restrict__ Wlo, const float* __restrict__ blo,
                            const float* __restrict__ Wro, const float* __restrict__ prelu_a) {
    __shared__ float sA[64], sC[64], sB[64];
    __shared__ float G[6][64];
    int t = threadIdx.x;  // 0..63
    // W_in shape (64, 66): col0 -> x1, col1 -> mask, rest hit h==0
    sA[t] = Win[t * 66 + 0];
    sC[t] = Win[t * 66 + 1];
    sB[t] = bin[t];
    __syncthreads();
    float g1 = 0, g2 = 0, g3 = 0, g4 = 0, g5 = 0, g6 = 0;
    for (int h = 0; h < 64; h++) {
        float w0 = Wgc[t * 128 + h];        // acts on z
        float w1 = Wgc[t * 128 + 64 + h];   // acts on zg
        g1 = fmaf(w0, sA[h], g1);
        g2 = fmaf(w0, sC[h], g2);
        g3 = fmaf(w0, sB[h], g3);
        g4 = fmaf(w1, sA[h], g4);
        g5 = fmaf(w1, sC[h], g5);
        g6 = fmaf(w1, sB[h], g6);
    }
    G[0][t] = g1;            // x1
    G[1][t] = g2;            // m
    G[2][t] = g4;            // u1
    G[3][t] = g5;            // u2
    G[4][t] = g6;            // s[j]
    G[5][t] = g3 + bgc[t];   // const
    __syncthreads();
    float r[6] = {0, 0, 0, 0, 0, 0};
    for (int o = 0; o < 64; o++) {
        float w = Wlo[t * 128 + o];  // second half of W_lo hits h==0
        r[0] = fmaf(w, G[0][o], r[0]);
        r[1] = fmaf(w, G[1][o], r[1]);
        r[2] = fmaf(w, G[2][o], r[2]);
        r[3] = fmaf(w, G[3][o], r[3]);
        r[4] = fmaf(w, G[4][o], r[4]);
        r[5] = fmaf(w, G[5][o], r[5]);
    }
    r[5] += blo[t];
    g_coef[0 * 64 + t] = r[0];
    g_coef[1 * 64 + t] = r[1];
    g_coef[2 * 64 + t] = r[2];
    g_coef[3 * 64 + t] = r[3];
    g_coef[4 * 64 + t] = r[4];
    g_coef[5 * 64 + t] = r[5];
    float wr = Wro[t];  // W_ro[0, 0:64] (cols 64..127 hit h==0)
    g_coef[6 * 64 + t] = wr;
    g_coef[7 * 64 + t] = wr * prelu_a[0];
}

// ---------------------------------------------------------------------------
// Kernel 2: s[j] = sum_n adj[n, j]
// ---------------------------------------------------------------------------
__global__ void colsum_kernel(const float* __restrict__ adj) {
    int lane = threadIdx.x & 31;
    int grp  = threadIdx.x >> 5;      // 0..7
    int j = blockIdx.x * 32 + lane;
    float s = 0.f;
    for (int n = grp; n < 1024; n += 8) s += adj[n * 1024 + j];
    __shared__ float red[8][32];
    red[grp][lane] = s;
    __syncthreads();
    if (grp == 0) {
        float tot = 0.f;
        #pragma unroll
        for (int k = 0; k < 8; k++) tot += red[k][lane];
        g_S[j] = tot;
    }
}

// ---------------------------------------------------------------------------
// Kernel 3: build X[i, c] with x1 in cols [0,512) and mask in cols [512,1024)
// ---------------------------------------------------------------------------
__global__ void buildX_kernel(const float* __restrict__ x, const int* __restrict__ mask,
                              const float* __restrict__ bfs) {
    int tid = blockIdx.x * 512 + threadIdx.x;  // 0 .. 524287
    int i = tid >> 9;          // node index (k-dim)
    int c = tid & 511;         // b*64 + t
    int b = c >> 6, t = c & 63;
    int src = b * (NN * TT) + i * TT + t;
    int m = mask[src];
    float bfs0 = bfs[0];
    float xv = x[src];
    g_X[i * 1024 + c]       = m ? xv : bfs0;
    g_X[i * 1024 + 512 + c] = (float)m;
}

// ---------------------------------------------------------------------------
// Kernel 4: U[j, c] = sum_i adj[i, j] * X[i, c]   (1024x1024x1024 fp32 TN GEMM)
// 64x64 tile, BK=16, 256 threads, 4x4 micro-tile per thread
// ---------------------------------------------------------------------------
__global__ __launch_bounds__(256) void sgemm_tn_kernel(const float* __restrict__ adj) {
    __shared__ float As[16][64];
    __shared__ float Bs[16][64];
    int j0 = blockIdx.y * 64;
    int c0 = blockIdx.x * 64;
    int tx = threadIdx.x & 15;
    int ty = threadIdx.x >> 4;
    float acc[4][4] = {};
    int lrow  = threadIdx.x >> 4;        // 0..15
    int lcol4 = (threadIdx.x & 15) * 4;  // 0..60
    for (int k0 = 0; k0 < 1024; k0 += 16) {
        float4 a = *(const float4*)&adj[(k0 + lrow) * 1024 + j0 + lcol4];
        float4 b = *(const float4*)&g_X[(k0 + lrow) * 1024 + c0 + lcol4];
        *(float4*)&As[lrow][lcol4] = a;
        *(float4*)&Bs[lrow][lcol4] = b;
        __syncthreads();
        #pragma unroll
        for (int kk = 0; kk < 16; kk++) {
            float4 av = *(float4*)&As[kk][ty * 4];
            float4 bv = *(float4*)&Bs[kk][tx * 4];
            acc[0][0] = fmaf(av.x, bv.x, acc[0][0]);
            acc[0][1] = fmaf(av.x, bv.y, acc[0][1]);
            acc[0][2] = fmaf(av.x, bv.z, acc[0][2]);
            acc[0][3] = fmaf(av.x, bv.w, acc[0][3]);
            acc[1][0] = fmaf(av.y, bv.x, acc[1][0]);
            acc[1][1] = fmaf(av.y, bv.y, acc[1][1]);
            acc[1][2] = fmaf(av.y, bv.z, acc[1][2]);
            acc[1][3] = fmaf(av.y, bv.w, acc[1][3]);
            acc[2][0] = fmaf(av.z, bv.x, acc[2][0]);
            acc[2][1] = fmaf(av.z, bv.y, acc[2][1]);
            acc[2][2] = fmaf(av.z, bv.z, acc[2][2]);
            acc[2][3] = fmaf(av.z, bv.w, acc[2][3]);
            acc[3][0] = fmaf(av.w, bv.x, acc[3][0]);
            acc[3][1] = fmaf(av.w, bv.y, acc[3][1]);
            acc[3][2] = fmaf(av.w, bv.z, acc[3][2]);
            acc[3][3] = fmaf(av.w, bv.w, acc[3][3]);
        }
        __syncthreads();
    }
    #pragma unroll
    for (int m = 0; m < 4; m++) {
        int j = j0 + ty * 4 + m;
        float4 v = make_float4(acc[m][0], acc[m][1], acc[m][2], acc[m][3]);
        *(float4*)&g_U[j * 1024 + c0 + tx * 4] = v;
    }
}

// ---------------------------------------------------------------------------
// Kernel 5: pointwise epilogue. Per element: 64-channel PReLU head + 64-wide MLP
// Each thread handles 4 consecutive t's (float4 along time).
// ---------------------------------------------------------------------------
__global__ __launch_bounds__(256) void epilogue_kernel(
    const float* __restrict__ x, const int* __restrict__ mask,
    const float* __restrict__ Wo1, const float* __restrict__ bo1,
    const float* __restrict__ Wo2, const float* __restrict__ bfs,
    const float* __restrict__ bro, const float* __restrict__ bo2,
    float* __restrict__ out) {
    __shared__ float sc[512];
    __shared__ float s1[64], s2[64], s3[64];
    int tid = threadIdx.x;
    for (int i = tid; i < 512; i += 256) sc[i] = g_coef[i];
    if (tid < 64) {
        s1[tid] = Wo1[tid];  // W_o1 shape (64,1)
        s2[tid] = bo1[tid];
        s3[tid] = Wo2[tid];  // W_o2 shape (1,64)
    }
    __syncthreads();
    float bfs0 = bfs[0], bro0 = bro[0], bo20 = bo2[0];

    int gid = blockIdx.x * 256 + tid;  // 0 .. 131071
    int e = gid * 4;
    int b = e >> 16;
    int rem = e & 65535;
    int j = rem >> 6;
    int tt = rem & 63;
    int c = b * 64 + tt;

    float4 xv = *(const float4*)&x[e];
    int4 mv = *(const int4*)&mask[e];
    const float* Ub = g_U + j * 1024 + c;
    float4 u1v = *(const float4*)Ub;
    float4 u2v = *(const float4*)(Ub + 512);
    float sj = g_S[j];

    float x1a[4], mfa[4], u1a[4], u2a[4];
    x1a[0] = mv.x ? xv.x : bfs0; mfa[0] = (float)mv.x;
    x1a[1] = mv.y ? xv.y : bfs0; mfa[1] = (float)mv.y;
    x1a[2] = mv.z ? xv.z : bfs0; mfa[2] = (float)mv.z;
    x1a[3] = mv.w ? xv.w : bfs0; mfa[3] = (float)mv.w;
    u1a[0] = u1v.x; u1a[1] = u1v.y; u1a[2] = u1v.z; u1a[3] = u1v.w;
    u2a[0] = u2v.x; u2a[1] = u2v.y; u2a[2] = u2v.z; u2a[3] = u2v.w;

    float acc[4] = {0.f, 0.f, 0.f, 0.f};
    #pragma unroll 8
    for (int h = 0; h < 64; h++) {
        float r1 = sc[h], r2 = sc[64 + h], r3 = sc[128 + h];
        float r4 = sc[192 + h], r5 = sc[256 + h], r6 = sc[320 + h];
        float wp = sc[384 + h], wn = sc[448 + h];
        float base = fmaf(r5, sj, r6);
        #pragma unroll
        for (int q = 0; q < 4; q++) {
            float v = fmaf(r1, x1a[q],
                      fmaf(r2, mfa[q],
                      fmaf(r3, u1a[q],
                      fmaf(r4, u2a[q], base))));
            acc[q] = fmaf((v >= 0.f) ? wp : wn, v, acc[q]);
        }
    }
    float res[4];
    #pragma unroll
    for (int q = 0; q < 4; q++) {
        float xs2 = acc[q] + bro0;
        float o = bo20;
        #pragma unroll 8
        for (int f = 0; f < 64; f++) {
            float y = fmaf(s1[f], xs2, s2[f]);
            y = fmaxf(y, 0.f);
            o = fmaf(s3[f], y, o);
        }
        res[q] = o;
    }
    *(float4*)&out[e] = make_float4(res[0], res[1], res[2], res[3]);
}

// ---------------------------------------------------------------------------
// Launch
// ---------------------------------------------------------------------------
extern "C" void kernel_launch(void* const* d_in, const int* in_sizes, int n_in,
                              void* d_out, int out_size) {
    const float* x      = (const float*)d_in[0];
    const int*   mask   = (const int*)  d_in[1];
    // d_in[2] = W_fs (unused: multiplies h == 0)
    const float* b_fs   = (const float*)d_in[3];
    const float* W_in   = (const float*)d_in[4];
    const float* b_in   = (const float*)d_in[5];
    const float* adj    = (const float*)d_in[6];
    const float* W_gc   = (const float*)d_in[7];
    const float* b_gc   = (const float*)d_in[8];
    const float* W_lo   = (const float*)d_in[9];
    const float* b_lo   = (const float*)d_in[10];
    const float* prelua = (const float*)d_in[11];
    const float* W_ro   = (const float*)d_in[12];
    const float* b_ro   = (const float*)d_in[13];
    const float* W_o1   = (const float*)d_in[14];
    const float* b_o1   = (const float*)d_in[15];
    const float* W_o2   = (const float*)d_in[16];
    const float* b_o2   = (const float*)d_in[17];
    float* out = (float*)d_out;

    coef_kernel<<<1, 64>>>(W_in, b_in, W_gc, b_gc, W_lo, b_lo, W_ro, prelua);
    colsum_kernel<<<32, 256>>>(adj);
    buildX_kernel<<<1024, 512>>>(x, mask, b_fs);
    dim3 ggrid(16, 16);
    sgemm_tn_kernel<<<ggrid, 256>>>(adj);
    epilogue_kernel<<<ELEMS / 4 / 256, 256>>>(x, mask, W_o1, b_o1, W_o2,
                                              b_fs, b_ro, b_o2, out);
}